// round 1
// baseline (speedup 1.0000x reference)
#include <cuda_runtime.h>

#define BATCH 4
#define NPTS  2048
#define KNN   16
#define BN_ALL (BATCH*NPTS)      // 8192
#define M_COLS (BN_ALL*3)        // 24576

// ------------------------- scratch (device globals; no mallocs) -------------
static __device__ __align__(16) float g_X0[BN_ALL*3];
static __device__ float g_sq[BN_ALL];
static __device__ int   g_idx[BN_ALL*KNN];
static __device__ float g_knnd[BN_ALL*64];
static __device__ int   g_knni[BN_ALL*64];
static __device__ __align__(16) float g_xcat240[BN_ALL*3*240];
static __device__ __align__(16) float g_xcat256[BN_ALL*3*256];
static __device__ __align__(16) float g_t128 [BN_ALL*3*128];
static __device__ __align__(16) float g_x0v  [BN_ALL*3*256];
static __device__ __align__(16) float g_Y    [BN_ALL*1536];   // reused per layer
static __device__ float g_dc  [M_COLS];
static __device__ float g_xm  [BATCH*3*128];
static __device__ float g_xmp [BATCH*3*32*128];
static __device__ float g_bias[BATCH*3*512];
static __device__ __align__(16) float g_W[512*256];

// ------------------------- helpers ------------------------------------------
__device__ __forceinline__ void lna3(float p0,float p1,float p2,
                                     float q0,float q1,float q2,
                                     float&o0,float&o1,float&o2)
{
    float dot = p0*q0 + p1*q1 + p2*q2;
    float dsq = q0*q0 + q1*q1 + q2*q2;
    float s = (dot < 0.f) ? 0.8f*dot/(dsq + 1e-6f) : 0.f;
    o0 = p0 - s*q0; o1 = p1 - s*q1; o2 = p2 - s*q2;
}

// ------------------------- prep: x (B,3,N) -> X0 (B,N,3), sq ----------------
__global__ void k_prep(const float* __restrict__ x)
{
    int i = blockIdx.x*blockDim.x + threadIdx.x;
    if (i >= BN_ALL) return;
    int b = i / NPTS, n = i - b*NPTS;
    float vx = x[(b*3+0)*NPTS + n];
    float vy = x[(b*3+1)*NPTS + n];
    float vz = x[(b*3+2)*NPTS + n];
    g_X0[i*3+0]=vx; g_X0[i*3+1]=vy; g_X0[i*3+2]=vz;
    g_sq[i] = fmaf(vz,vz, fmaf(vy,vy, vx*vx));
}

// ------------------------- KNN: split scan (4 chunks) + merge ---------------
__global__ void k_knn_part()
{
    int t = blockIdx.x*blockDim.x + threadIdx.x;    // 32768 threads
    if (t >= BN_ALL*4) return;
    int bn    = t & (BN_ALL-1);
    int chunk = t >> 13;
    int b = bn / NPTS;
    float px = g_X0[bn*3], py = g_X0[bn*3+1], pz = g_X0[bn*3+2];
    float sn = g_sq[bn];
    const float* Xb = g_X0 + b*NPTS*3;
    const float* Sb = g_sq + b*NPTS;

    float bd[KNN]; int bi[KNN];
    #pragma unroll
    for (int i = 0; i < KNN; i++){ bd[i] = 3.4e38f; bi[i] = 0; }

    int m0 = chunk*512;
    for (int mm = 0; mm < 512; mm++){
        int m = m0 + mm;
        float qx = Xb[m*3], qy = Xb[m*3+1], qz = Xb[m*3+2];
        float dot = fmaf(pz,qz, fmaf(py,qy, px*qx));
        float d2  = (sn + Sb[m]) - 2.f*dot;
        if (d2 < bd[KNN-1]){
            int p = KNN-1;
            while (p > 0 && bd[p-1] > d2){ bd[p]=bd[p-1]; bi[p]=bi[p-1]; p--; }
            bd[p] = d2; bi[p] = m;
        }
    }
    for (int i = 0; i < KNN; i++){
        g_knnd[bn*64 + chunk*16 + i] = bd[i];
        g_knni[bn*64 + chunk*16 + i] = bi[i];
    }
}

__global__ void k_knn_merge()
{
    int bn = blockIdx.x*blockDim.x + threadIdx.x;
    if (bn >= BN_ALL) return;
    float bd[KNN]; int bi[KNN];
    #pragma unroll
    for (int i = 0; i < KNN; i++){ bd[i] = 3.4e38f; bi[i] = 0; }
    for (int e = 0; e < 64; e++){
        float d2 = g_knnd[bn*64 + e];
        int   m  = g_knni[bn*64 + e];
        if (d2 < bd[KNN-1]){
            int p = KNN-1;
            while (p > 0 && bd[p-1] > d2){ bd[p]=bd[p-1]; bi[p]=bi[p-1]; p--; }
            bd[p] = d2; bi[p] = m;
        }
    }
    for (int i = 0; i < KNN; i++) g_idx[bn*KNN + i] = bi[i];
}

// ------------------------- layer 1 direct Y build (C=1, O=16) ---------------
__global__ void k_layer1(const float* __restrict__ w1f, const float* __restrict__ w1d)
{
    int t = blockIdx.x*blockDim.x + threadIdx.x;
    if (t >= BN_ALL*16) return;
    int bn = t >> 4, o = t & 15;
    float x0 = g_X0[bn*3], x1 = g_X0[bn*3+1], x2 = g_X0[bn*3+2];
    float wf0 = w1f[o*2], wf1 = w1f[o*2+1];
    float wd0 = w1d[o*2], wd1 = w1d[o*2+1];
    float r[4] = { wf0, wf1 - wf0, wd0, wd1 - wd0 };
    float* Y = g_Y + (size_t)bn*192;          // 4 groups * 3 * 16
    #pragma unroll
    for (int g = 0; g < 4; g++){
        Y[(g*3+0)*16 + o] = r[g]*x0;
        Y[(g*3+1)*16 + o] = r[g]*x1;
        Y[(g*3+2)*16 + o] = r[g]*x2;
    }
}

// ------------------------- weight combiners ---------------------------------
__global__ void k_wcomb_graph(const float* __restrict__ Wf, const float* __restrict__ Wd,
                              int C, int O)
{
    int t = blockIdx.x*blockDim.x + threadIdx.x;
    if (t >= 4*O*C) return;
    int r = t / C, c = t - r*C;
    int g = r / O, o = r - g*O;
    float v;
    if      (g == 0) v = Wf[o*2*C + c];
    else if (g == 1) v = Wf[o*2*C + C + c] - Wf[o*2*C + c];
    else if (g == 2) v = Wd[o*2*C + c];
    else             v = Wd[o*2*C + C + c] - Wd[o*2*C + c];
    g_W[(size_t)r*C + c] = v;
}

__global__ void k_wcomb_c(const float* __restrict__ wcf)
{
    int t = blockIdx.x*blockDim.x + threadIdx.x;
    if (t < 128*240) g_W[t] = wcf[t];
}

__global__ void k_wcomb_i1(const float* __restrict__ wi1f, const float* __restrict__ wi1d)
{
    int t = blockIdx.x*blockDim.x + threadIdx.x;
    if (t >= 256*128) return;
    int r = t >> 7, c = t & 127;
    g_W[t] = (r < 128) ? wi1f[r*256 + c] : wi1d[(r-128)*256 + c];
}

__global__ void k_wcomb_i2(const float* __restrict__ wi2f, const float* __restrict__ wi2d)
{
    int t = blockIdx.x*blockDim.x + threadIdx.x;
    if (t >= 512*128) return;
    int r = t >> 7, c = t & 127;
    g_W[t] = (r < 256) ? wi2f[r*128 + c] : wi2d[(r-256)*128 + c];
}

// ------------------------- generic tiled SGEMM ------------------------------
// Out[r][m] = sum_c g_W[r][c] * X[m*CS + co + c],   m in [0, 24576)
// Written to g_Y at ((bn*G + r/O)*3 + d)*O + r%O  with m = bn*3 + d.
__global__ void __launch_bounds__(256) k_gemm(int xsel, int useBias,
                                              int R, int C, int CS, int co,
                                              int G, int O)
{
    __shared__ __align__(16) float Ws[16][64];
    __shared__ __align__(16) float Xs[16][64];
    const float* __restrict__ X = (xsel==0) ? g_xcat240 : (xsel==1) ? g_xcat256 : g_t128;

    int m0 = blockIdx.x*64, r0 = blockIdx.y*64;
    int t  = threadIdx.x;
    int tr = t >> 4, tc = t & 15;

    float acc[4][4];
    #pragma unroll
    for (int i = 0; i < 4; i++)
        #pragma unroll
        for (int j = 0; j < 4; j++) acc[i][j] = 0.f;

    for (int k0 = 0; k0 < C; k0 += 16){
        #pragma unroll
        for (int rep = 0; rep < 4; rep++){
            int ii = rep*256 + t;
            int r = ii >> 4, k = ii & 15;
            Ws[k][r] = g_W[(size_t)(r0+r)*C + k0 + k];
        }
        {
            int mloc = t >> 2, kq = t & 3;
            const float* xp = X + (size_t)(m0+mloc)*CS + co + k0 + kq*4;
            float4 v = *(const float4*)xp;
            Xs[kq*4+0][mloc]=v.x; Xs[kq*4+1][mloc]=v.y;
            Xs[kq*4+2][mloc]=v.z; Xs[kq*4+3][mloc]=v.w;
        }
        __syncthreads();
        #pragma unroll
        for (int k = 0; k < 16; k++){
            float4 a  = *(const float4*)&Ws[k][tr*4];
            float4 bb = *(const float4*)&Xs[k][tc*4];
            float av[4] = {a.x,a.y,a.z,a.w};
            float bv[4] = {bb.x,bb.y,bb.z,bb.w};
            #pragma unroll
            for (int i = 0; i < 4; i++)
                #pragma unroll
                for (int j = 0; j < 4; j++)
                    acc[i][j] = fmaf(av[i], bv[j], acc[i][j]);
        }
        __syncthreads();
    }

    #pragma unroll
    for (int i = 0; i < 4; i++){
        int r = r0 + tr*4 + i;
        int g = r / O, o = r - g*O;
        #pragma unroll
        for (int j = 0; j < 4; j++){
            int m  = m0 + tc*4 + j;
            int bn = m / 3, d = m - bn*3;
            float v = acc[i][j];
            if (useBias){
                int b = m / (3*NPTS);
                v += g_bias[(b*3 + d)*R + r];
            }
            g_Y[(size_t)((bn*G + g)*3 + d)*O + o] = v;
        }
    }
}

// ------------------------- gather + vec-LNA + mean over K -------------------
template<int O, int PPB>
__global__ void __launch_bounds__(256) k_gather(int co)
{
    __shared__ int sidx[PPB*KNN];
    int t  = threadIdx.x;
    int p0 = blockIdx.x * PPB;
    if (t < PPB*KNN) sidx[t] = g_idx[p0*KNN + t];
    __syncthreads();

    int pl = t / O;
    int o  = t - pl*O;
    int bn = p0 + pl;
    int jbase = (bn / NPTS) * NPTS;

    const float* Z = g_Y + (size_t)bn*12*O;
    float zp0=Z[(3+0)*O+o], zp1=Z[(3+1)*O+o], zp2=Z[(3+2)*O+o];
    float zq0=Z[(9+0)*O+o], zq1=Z[(9+1)*O+o], zq2=Z[(9+2)*O+o];
    float a0=0.f, a1=0.f, a2=0.f;

    #pragma unroll 4
    for (int k = 0; k < KNN; k++){
        int j = jbase + sidx[pl*KNN + k];
        const float* Yj = g_Y + (size_t)j*12*O;
        float p0v = Yj[0*O+o] + zp0;
        float p1v = Yj[1*O+o] + zp1;
        float p2v = Yj[2*O+o] + zp2;
        float q0  = Yj[6*O+o] + zq0;
        float q1  = Yj[7*O+o] + zq1;
        float q2  = Yj[8*O+o] + zq2;
        float dot = p0v*q0 + p1v*q1 + p2v*q2;
        float dsq = q0*q0 + q1*q1 + q2*q2;
        float s = (dot < 0.f) ? 0.8f*dot/(dsq + 1e-6f) : 0.f;
        a0 += p0v - s*q0; a1 += p1v - s*q1; a2 += p2v - s*q2;
    }
    float* out = g_xcat240 + (size_t)bn*3*240 + co + o;
    out[0]   = a0*0.0625f;
    out[240] = a1*0.0625f;
    out[480] = a2*0.0625f;
}

// ------------------------- layer c: dc GEMV (1x240) -------------------------
__global__ void k_dc(const float* __restrict__ wcd)
{
    int gt = blockIdx.x*blockDim.x + threadIdx.x;
    int warp = gt >> 5, lane = gt & 31;
    if (warp >= M_COLS) return;
    const float* row = g_xcat240 + (size_t)warp*240;
    float s = 0.f;
    for (int c = lane; c < 240; c += 32) s = fmaf(row[c], wcd[c], s);
    #pragma unroll
    for (int off = 16; off; off >>= 1) s += __shfl_xor_sync(0xffffffffu, s, off);
    if (lane == 0) g_dc[warp] = s;
}

// layer c LNA (q shared across o), writes xcat256 channels [0,128)
__global__ void k_lna_c()
{
    int t = blockIdx.x*blockDim.x + threadIdx.x;
    if (t >= BN_ALL*128) return;
    int bn = t >> 7, o = t & 127;
    const float* Yb = g_Y + (size_t)bn*384;
    float p0 = Yb[0*128+o], p1 = Yb[1*128+o], p2 = Yb[2*128+o];
    float q0 = g_dc[bn*3+0], q1 = g_dc[bn*3+1], q2 = g_dc[bn*3+2];
    float o0,o1,o2; lna3(p0,p1,p2,q0,q1,q2,o0,o1,o2);
    float* out = g_xcat256 + (size_t)bn*3*256 + o;
    out[0] = o0; out[256] = o1; out[512] = o2;
}

// ------------------------- xm mean + broadcast ------------------------------
__global__ void k_xm_part()
{
    int blk  = blockIdx.x;              // BATCH*3*32
    int slab = blk & 31;
    int bd3  = blk >> 5;
    int b = bd3 / 3, d = bd3 - b*3;
    int o = threadIdx.x;                // 128
    float s = 0.f;
    for (int nn = 0; nn < 64; nn++){
        int n = slab*64 + nn;
        s += g_xcat256[((size_t)(b*NPTS+n)*3 + d)*256 + o];
    }
    g_xmp[(size_t)(bd3*32 + slab)*128 + o] = s;
}

__global__ void k_xm_final()
{
    int t = blockIdx.x*blockDim.x + threadIdx.x;
    if (t >= BATCH*3*128) return;
    int bd3 = t >> 7, o = t & 127;
    float s = 0.f;
    for (int sl = 0; sl < 32; sl++) s += g_xmp[(size_t)(bd3*32+sl)*128 + o];
    g_xm[bd3*128 + o] = s * (1.f/2048.f);
}

__global__ void k_bcast()
{
    int t = blockIdx.x*blockDim.x + threadIdx.x;
    if (t >= BN_ALL*384) return;
    int bn = t / 384, r = t - bn*384;
    int d = r >> 7, o = r & 127;
    int b = bn / NPTS;
    g_xcat256[((size_t)bn*3 + d)*256 + 128 + o] = g_xm[(b*3+d)*128 + o];
}

// bias for i1 from xm constant half of xcat256
__global__ void k_bias_i1(const float* __restrict__ wi1f, const float* __restrict__ wi1d)
{
    int t = blockIdx.x*blockDim.x + threadIdx.x;
    if (t >= BATCH*3*256) return;
    int bd3 = t >> 8, r = t & 255;
    const float* wrow = (r < 128) ? (wi1f + r*256) : (wi1d + (r-128)*256);
    float s = 0.f;
    for (int c = 0; c < 128; c++) s = fmaf(wrow[128+c], g_xm[bd3*128 + c], s);
    g_bias[bd3*256 + r] = s;
}

// ------------------------- plain p/q LNA (G=2 GEMM output) ------------------
__global__ void k_lna_pd(int O, int osel)
{
    int t = blockIdx.x*blockDim.x + threadIdx.x;
    if (t >= BN_ALL*O) return;
    int bn = t / O, o = t - (t/O)*O;
    const float* Yb = g_Y + (size_t)bn*6*O;
    float p0=Yb[0*O+o], p1=Yb[1*O+o], p2=Yb[2*O+o];
    float q0=Yb[3*O+o], q1=Yb[4*O+o], q2=Yb[5*O+o];
    float o0,o1,o2; lna3(p0,p1,p2,q0,q1,q2,o0,o1,o2);
    if (osel == 0){
        float* out = g_t128 + (size_t)bn*3*128 + o;
        out[0]=o0; out[128]=o1; out[256]=o2;
    } else {
        float* out = g_x0v + (size_t)bn*3*256 + o;
        out[0]=o0; out[256]=o1; out[512]=o2;
    }
}

// ------------------------- final invariant ----------------------------------
__global__ void __launch_bounds__(256) k_inv(float* __restrict__ out)
{
    __shared__ float tile[256*33];
    int n0 = blockIdx.x * 32;          // global bn tile (never crosses batch)
    int t  = threadIdx.x;              // o = t
    for (int p = 0; p < 32; p++){
        size_t base = (size_t)(n0 + p)*3*256;
        float s = g_xcat256[base       + t]*g_x0v[base       + t]
                + g_xcat256[base + 256 + t]*g_x0v[base + 256 + t]
                + g_xcat256[base + 512 + t]*g_x0v[base + 512 + t];
        tile[t*33 + p] = s;
    }
    __syncthreads();
    int b   = n0 / NPTS;
    int nn0 = n0 - b*NPTS;
    int p   = t & 31, og = t >> 5;     // 8 o-groups
    for (int o = og; o < 256; o += 8)
        out[(size_t)(b*256 + o)*NPTS + nn0 + p] = tile[o*33 + p];
}

// ------------------------- launcher -----------------------------------------
extern "C" void kernel_launch(void* const* d_in, const int* in_sizes, int n_in,
                              void* d_out, int out_size)
{
    const float* x    = (const float*)d_in[0];
    const float* w1f  = (const float*)d_in[1];
    const float* w1d  = (const float*)d_in[2];
    const float* w2f  = (const float*)d_in[3];
    const float* w2d  = (const float*)d_in[4];
    const float* w3f  = (const float*)d_in[5];
    const float* w3d  = (const float*)d_in[6];
    const float* w4f  = (const float*)d_in[7];
    const float* w4d  = (const float*)d_in[8];
    const float* wcf  = (const float*)d_in[9];
    const float* wcd  = (const float*)d_in[10];
    const float* wi1f = (const float*)d_in[11];
    const float* wi1d = (const float*)d_in[12];
    const float* wi2f = (const float*)d_in[13];
    const float* wi2d = (const float*)d_in[14];
    float* out = (float*)d_out;

    k_prep<<<(BN_ALL+127)/128, 128>>>(x);
    k_knn_part<<<(BN_ALL*4+127)/128, 128>>>();
    k_knn_merge<<<(BN_ALL+127)/128, 128>>>();

    // ---- layer 1 (C=1 -> O=16)
    k_layer1<<<(BN_ALL*16+255)/256, 256>>>(w1f, w1d);
    k_gather<16,16><<<BN_ALL/16, 256>>>(0);

    // ---- layer 2 (C=16 -> O=32)
    k_wcomb_graph<<<(4*32*16+255)/256, 256>>>(w2f, w2d, 16, 32);
    k_gemm<<<dim3(M_COLS/64, 128/64), 256>>>(0, 0, 128, 16, 240, 0, 4, 32);
    k_gather<32,8><<<BN_ALL/8, 256>>>(16);

    // ---- layer 3 (C=32 -> O=64)
    k_wcomb_graph<<<(4*64*32+255)/256, 256>>>(w3f, w3d, 32, 64);
    k_gemm<<<dim3(M_COLS/64, 256/64), 256>>>(0, 0, 256, 32, 240, 16, 4, 64);
    k_gather<64,4><<<BN_ALL/4, 256>>>(48);

    // ---- layer 4 (C=64 -> O=128)
    k_wcomb_graph<<<(4*128*64+255)/256, 256>>>(w4f, w4d, 64, 128);
    k_gemm<<<dim3(M_COLS/64, 512/64), 256>>>(0, 0, 512, 64, 240, 48, 4, 128);
    k_gather<128,2><<<BN_ALL/2, 256>>>(112);

    // ---- concat layer (wcf 128x240, wcd 1x240)
    k_wcomb_c<<<(128*240+255)/256, 256>>>(wcf);
    k_gemm<<<dim3(M_COLS/64, 128/64), 256>>>(0, 0, 128, 240, 240, 0, 1, 128);
    k_dc<<<(M_COLS*32+255)/256, 256>>>(wcd);
    k_lna_c<<<(BN_ALL*128+255)/256, 256>>>();

    // ---- xm mean over N + broadcast into channels [128,256)
    k_xm_part<<<BATCH*3*32, 128>>>();
    k_xm_final<<<(BATCH*3*128+255)/256, 256>>>();
    k_bcast<<<(BN_ALL*384+255)/256, 256>>>();

    // ---- i1 (wi1f/wi1d 128x256; contract 128 + xm bias)
    k_wcomb_i1<<<(256*128+255)/256, 256>>>(wi1f, wi1d);
    k_bias_i1<<<(BATCH*3*256+255)/256, 256>>>(wi1f, wi1d);
    k_gemm<<<dim3(M_COLS/64, 256/64), 256>>>(1, 1, 256, 128, 256, 0, 2, 128);
    k_lna_pd<<<(BN_ALL*128+255)/256, 256>>>(128, 0);

    // ---- i2 (wi2f/wi2d 256x128)
    k_wcomb_i2<<<(512*128+255)/256, 256>>>(wi2f, wi2d);
    k_gemm<<<dim3(M_COLS/64, 512/64), 256>>>(2, 0, 512, 128, 128, 0, 2, 256);
    k_lna_pd<<<(BN_ALL*256+255)/256, 256>>>(256, 1);

    // ---- invariant output (B,256,N)
    k_inv<<<BN_ALL/32, 256>>>(out);
}

// round 2
// speedup vs baseline: 1.1421x; 1.1421x over previous
#include <cuda_runtime.h>

#define BATCH 4
#define NPTS  2048
#define KNN   16
#define BN_ALL (BATCH*NPTS)      // 8192
#define M_COLS (BN_ALL*3)        // 24576

// ------------------------- scratch (device globals; no mallocs) -------------
static __device__ __align__(16) float g_X0[BN_ALL*3];
static __device__ float g_sq[BN_ALL];
static __device__ int   g_idx[BN_ALL*KNN];
static __device__ float g_knnd[BN_ALL*64];
static __device__ int   g_knni[BN_ALL*64];
static __device__ __align__(16) float g_xcat240[BN_ALL*3*240];
static __device__ __align__(16) float g_xcat256[BN_ALL*3*256];
static __device__ __align__(16) float g_t128 [BN_ALL*3*128];
static __device__ __align__(16) float g_x0v  [BN_ALL*3*256];
static __device__ __align__(16) float g_Y    [BN_ALL*1536];   // reused per layer
static __device__ float g_dc  [M_COLS];
static __device__ float g_xm  [BATCH*3*128];
static __device__ float g_xmp [BATCH*3*32*128];
static __device__ float g_bias[BATCH*3*512];
static __device__ __align__(16) float g_W[512*256];

// ------------------------- helpers ------------------------------------------
__device__ __forceinline__ void lna3(float p0,float p1,float p2,
                                     float q0,float q1,float q2,
                                     float&o0,float&o1,float&o2)
{
    float dot = p0*q0 + p1*q1 + p2*q2;
    float dsq = q0*q0 + q1*q1 + q2*q2;
    float s = (dot < 0.f) ? 0.8f*dot/(dsq + 1e-6f) : 0.f;
    o0 = p0 - s*q0; o1 = p1 - s*q1; o2 = p2 - s*q2;
}

// ------------------------- prep: x (B,3,N) -> X0 (B,N,3), sq ----------------
__global__ void k_prep(const float* __restrict__ x)
{
    int i = blockIdx.x*blockDim.x + threadIdx.x;
    if (i >= BN_ALL) return;
    int b = i / NPTS, n = i - b*NPTS;
    float vx = x[(b*3+0)*NPTS + n];
    float vy = x[(b*3+1)*NPTS + n];
    float vz = x[(b*3+2)*NPTS + n];
    g_X0[i*3+0]=vx; g_X0[i*3+1]=vy; g_X0[i*3+2]=vz;
    g_sq[i] = fmaf(vz,vz, fmaf(vy,vy, vx*vx));
}

// ------------------------- KNN: split scan (4 chunks) + merge ---------------
__global__ void k_knn_part()
{
    int t = blockIdx.x*blockDim.x + threadIdx.x;    // 32768 threads
    if (t >= BN_ALL*4) return;
    int bn    = t & (BN_ALL-1);
    int chunk = t >> 13;
    int b = bn / NPTS;
    float px = g_X0[bn*3], py = g_X0[bn*3+1], pz = g_X0[bn*3+2];
    float sn = g_sq[bn];
    const float* Xb = g_X0 + b*NPTS*3;
    const float* Sb = g_sq + b*NPTS;

    float bd[KNN]; int bi[KNN];
    #pragma unroll
    for (int i = 0; i < KNN; i++){ bd[i] = 3.4e38f; bi[i] = 0; }

    int m0 = chunk*512;
    for (int mm = 0; mm < 512; mm++){
        int m = m0 + mm;
        float qx = Xb[m*3], qy = Xb[m*3+1], qz = Xb[m*3+2];
        float dot = fmaf(pz,qz, fmaf(py,qy, px*qx));
        float d2  = (sn + Sb[m]) - 2.f*dot;
        if (d2 < bd[KNN-1]){
            int p = KNN-1;
            while (p > 0 && bd[p-1] > d2){ bd[p]=bd[p-1]; bi[p]=bi[p-1]; p--; }
            bd[p] = d2; bi[p] = m;
        }
    }
    for (int i = 0; i < KNN; i++){
        g_knnd[bn*64 + chunk*16 + i] = bd[i];
        g_knni[bn*64 + chunk*16 + i] = bi[i];
    }
}

__global__ void k_knn_merge()
{
    int bn = blockIdx.x*blockDim.x + threadIdx.x;
    if (bn >= BN_ALL) return;
    float bd[KNN]; int bi[KNN];
    #pragma unroll
    for (int i = 0; i < KNN; i++){ bd[i] = 3.4e38f; bi[i] = 0; }
    for (int e = 0; e < 64; e++){
        float d2 = g_knnd[bn*64 + e];
        int   m  = g_knni[bn*64 + e];
        if (d2 < bd[KNN-1]){
            int p = KNN-1;
            while (p > 0 && bd[p-1] > d2){ bd[p]=bd[p-1]; bi[p]=bi[p-1]; p--; }
            bd[p] = d2; bi[p] = m;
        }
    }
    for (int i = 0; i < KNN; i++) g_idx[bn*KNN + i] = bi[i];
}

// ------------------------- layer 1 direct Y build (C=1, O=16) ---------------
__global__ void k_layer1(const float* __restrict__ w1f, const float* __restrict__ w1d)
{
    int t = blockIdx.x*blockDim.x + threadIdx.x;
    if (t >= BN_ALL*16) return;
    int bn = t >> 4, o = t & 15;
    float x0 = g_X0[bn*3], x1 = g_X0[bn*3+1], x2 = g_X0[bn*3+2];
    float wf0 = w1f[o*2], wf1 = w1f[o*2+1];
    float wd0 = w1d[o*2], wd1 = w1d[o*2+1];
    float r[4] = { wf0, wf1 - wf0, wd0, wd1 - wd0 };
    float* Y = g_Y + (size_t)bn*192;          // 4 groups * 3 * 16
    #pragma unroll
    for (int g = 0; g < 4; g++){
        Y[(g*3+0)*16 + o] = r[g]*x0;
        Y[(g*3+1)*16 + o] = r[g]*x1;
        Y[(g*3+2)*16 + o] = r[g]*x2;
    }
}

// ------------------------- weight combiners ---------------------------------
__global__ void k_wcomb_graph(const float* __restrict__ Wf, const float* __restrict__ Wd,
                              int C, int O)
{
    int t = blockIdx.x*blockDim.x + threadIdx.x;
    if (t >= 4*O*C) return;
    int r = t / C, c = t - r*C;
    int g = r / O, o = r - g*O;
    float v;
    if      (g == 0) v = Wf[o*2*C + c];
    else if (g == 1) v = Wf[o*2*C + C + c] - Wf[o*2*C + c];
    else if (g == 2) v = Wd[o*2*C + c];
    else             v = Wd[o*2*C + C + c] - Wd[o*2*C + c];
    g_W[(size_t)r*C + c] = v;
}

__global__ void k_wcomb_c(const float* __restrict__ wcf)
{
    int t = blockIdx.x*blockDim.x + threadIdx.x;
    if (t < 128*240) g_W[t] = wcf[t];
}

__global__ void k_wcomb_i1(const float* __restrict__ wi1f, const float* __restrict__ wi1d)
{
    int t = blockIdx.x*blockDim.x + threadIdx.x;
    if (t >= 256*128) return;
    int r = t >> 7, c = t & 127;
    g_W[t] = (r < 128) ? wi1f[r*256 + c] : wi1d[(r-128)*256 + c];
}

__global__ void k_wcomb_i2(const float* __restrict__ wi2f, const float* __restrict__ wi2d)
{
    int t = blockIdx.x*blockDim.x + threadIdx.x;
    if (t >= 512*128) return;
    int r = t >> 7, c = t & 127;
    g_W[t] = (r < 256) ? wi2f[r*128 + c] : wi2d[(r-256)*128 + c];
}

// ------------------------- 128x128 tiled SGEMM, 8x8 per thread --------------
// Out[r][m] = sum_c g_W[r][c] * X[m*CS + co + c],   m in [0, 24576)
// Written to g_Y at ((bn*G + r/O)*3 + d)*O + r%O  with m = bn*3 + d.
__global__ void __launch_bounds__(256,2) k_gemm(int xsel, int useBias,
                                                int R, int C, int CS, int co,
                                                int G, int O)
{
    __shared__ __align__(16) float Ws[16][132];
    __shared__ __align__(16) float Xs[16][132];
    const float* __restrict__ X = (xsel==0) ? g_xcat240 : (xsel==1) ? g_xcat256 : g_t128;

    int m0 = blockIdx.x*128, r0 = blockIdx.y*128;
    int t  = threadIdx.x;
    int tx = t & 15, ty = t >> 4;

    float acc[2][2][4][4];
    #pragma unroll
    for (int a = 0; a < 2; a++)
        #pragma unroll
        for (int b = 0; b < 2; b++)
            #pragma unroll
            for (int i = 0; i < 4; i++)
                #pragma unroll
                for (int j = 0; j < 4; j++) acc[a][b][i][j] = 0.f;

    int lr  = t >> 2;          // 0..63
    int lk4 = (t & 3) * 4;     // 0,4,8,12

    for (int k0 = 0; k0 < C; k0 += 16){
        float4 w0 = *(const float4*)&g_W[(size_t)(r0+lr   )*C + k0 + lk4];
        float4 w1 = *(const float4*)&g_W[(size_t)(r0+lr+64)*C + k0 + lk4];
        float4 v0 = *(const float4*)&X  [(size_t)(m0+lr   )*CS + co + k0 + lk4];
        float4 v1 = *(const float4*)&X  [(size_t)(m0+lr+64)*CS + co + k0 + lk4];
        Ws[lk4+0][lr]=w0.x; Ws[lk4+1][lr]=w0.y; Ws[lk4+2][lr]=w0.z; Ws[lk4+3][lr]=w0.w;
        Ws[lk4+0][lr+64]=w1.x; Ws[lk4+1][lr+64]=w1.y; Ws[lk4+2][lr+64]=w1.z; Ws[lk4+3][lr+64]=w1.w;
        Xs[lk4+0][lr]=v0.x; Xs[lk4+1][lr]=v0.y; Xs[lk4+2][lr]=v0.z; Xs[lk4+3][lr]=v0.w;
        Xs[lk4+0][lr+64]=v1.x; Xs[lk4+1][lr+64]=v1.y; Xs[lk4+2][lr+64]=v1.z; Xs[lk4+3][lr+64]=v1.w;
        __syncthreads();
        #pragma unroll
        for (int k = 0; k < 16; k++){
            float4 a0 = *(const float4*)&Ws[k][ty*4];
            float4 a1 = *(const float4*)&Ws[k][64 + ty*4];
            float4 b0 = *(const float4*)&Xs[k][tx*4];
            float4 b1 = *(const float4*)&Xs[k][64 + tx*4];
            float av[2][4] = {{a0.x,a0.y,a0.z,a0.w},{a1.x,a1.y,a1.z,a1.w}};
            float bv[2][4] = {{b0.x,b0.y,b0.z,b0.w},{b1.x,b1.y,b1.z,b1.w}};
            #pragma unroll
            for (int a = 0; a < 2; a++)
                #pragma unroll
                for (int i = 0; i < 4; i++)
                    #pragma unroll
                    for (int b = 0; b < 2; b++)
                        #pragma unroll
                        for (int j = 0; j < 4; j++)
                            acc[a][b][i][j] = fmaf(av[a][i], bv[b][j], acc[a][b][i][j]);
        }
        __syncthreads();
    }

    #pragma unroll
    for (int a = 0; a < 2; a++)
        #pragma unroll
        for (int i = 0; i < 4; i++){
            int r = r0 + a*64 + ty*4 + i;
            int g = r / O, o = r - g*O;
            #pragma unroll
            for (int b = 0; b < 2; b++)
                #pragma unroll
                for (int j = 0; j < 4; j++){
                    int m  = m0 + b*64 + tx*4 + j;
                    int bn = m / 3, d = m - bn*3;
                    float v = acc[a][b][i][j];
                    if (useBias){
                        int bb = m / (3*NPTS);
                        v += g_bias[(bb*3 + d)*R + r];
                    }
                    g_Y[(size_t)((bn*G + g)*3 + d)*O + o] = v;
                }
        }
}

// ------------------------- gather + vec-LNA + mean over K -------------------
template<int O, int PPB>
__global__ void __launch_bounds__(256) k_gather(int co)
{
    __shared__ int sidx[PPB*KNN];
    int t  = threadIdx.x;
    int p0 = blockIdx.x * PPB;
    if (t < PPB*KNN) sidx[t] = g_idx[p0*KNN + t];
    __syncthreads();

    int pl = t / O;
    int o  = t - pl*O;
    int bn = p0 + pl;
    int jbase = (bn / NPTS) * NPTS;

    const float* Z = g_Y + (size_t)bn*12*O;
    float zp0=Z[(3+0)*O+o], zp1=Z[(3+1)*O+o], zp2=Z[(3+2)*O+o];
    float zq0=Z[(9+0)*O+o], zq1=Z[(9+1)*O+o], zq2=Z[(9+2)*O+o];
    float a0=0.f, a1=0.f, a2=0.f;

    #pragma unroll 4
    for (int k = 0; k < KNN; k++){
        int j = jbase + sidx[pl*KNN + k];
        const float* Yj = g_Y + (size_t)j*12*O;
        float p0v = Yj[0*O+o] + zp0;
        float p1v = Yj[1*O+o] + zp1;
        float p2v = Yj[2*O+o] + zp2;
        float q0  = Yj[6*O+o] + zq0;
        float q1  = Yj[7*O+o] + zq1;
        float q2  = Yj[8*O+o] + zq2;
        float dot = p0v*q0 + p1v*q1 + p2v*q2;
        float dsq = q0*q0 + q1*q1 + q2*q2;
        float s = (dot < 0.f) ? 0.8f*dot/(dsq + 1e-6f) : 0.f;
        a0 += p0v - s*q0; a1 += p1v - s*q1; a2 += p2v - s*q2;
    }
    float* out = g_xcat240 + (size_t)bn*3*240 + co + o;
    out[0]   = a0*0.0625f;
    out[240] = a1*0.0625f;
    out[480] = a2*0.0625f;
}

// ------------------------- layer c: dc GEMV (1x240) -------------------------
__global__ void k_dc(const float* __restrict__ wcd)
{
    int gt = blockIdx.x*blockDim.x + threadIdx.x;
    int warp = gt >> 5, lane = gt & 31;
    if (warp >= M_COLS) return;
    const float* row = g_xcat240 + (size_t)warp*240;
    float s = 0.f;
    for (int c = lane; c < 240; c += 32) s = fmaf(row[c], wcd[c], s);
    #pragma unroll
    for (int off = 16; off; off >>= 1) s += __shfl_xor_sync(0xffffffffu, s, off);
    if (lane == 0) g_dc[warp] = s;
}

// layer c LNA (q shared across o), writes xcat256 channels [0,128)
__global__ void k_lna_c()
{
    int t = blockIdx.x*blockDim.x + threadIdx.x;
    if (t >= BN_ALL*128) return;
    int bn = t >> 7, o = t & 127;
    const float* Yb = g_Y + (size_t)bn*384;
    float p0 = Yb[0*128+o], p1 = Yb[1*128+o], p2 = Yb[2*128+o];
    float q0 = g_dc[bn*3+0], q1 = g_dc[bn*3+1], q2 = g_dc[bn*3+2];
    float o0,o1,o2; lna3(p0,p1,p2,q0,q1,q2,o0,o1,o2);
    float* out = g_xcat256 + (size_t)bn*3*256 + o;
    out[0] = o0; out[256] = o1; out[512] = o2;
}

// ------------------------- xm mean + broadcast ------------------------------
__global__ void k_xm_part()
{
    int blk  = blockIdx.x;              // BATCH*3*32
    int slab = blk & 31;
    int bd3  = blk >> 5;
    int b = bd3 / 3, d = bd3 - b*3;
    int o = threadIdx.x;                // 128
    float s = 0.f;
    for (int nn = 0; nn < 64; nn++){
        int n = slab*64 + nn;
        s += g_xcat256[((size_t)(b*NPTS+n)*3 + d)*256 + o];
    }
    g_xmp[(size_t)(bd3*32 + slab)*128 + o] = s;
}

__global__ void k_xm_final()
{
    int t = blockIdx.x*blockDim.x + threadIdx.x;
    if (t >= BATCH*3*128) return;
    int bd3 = t >> 7, o = t & 127;
    float s = 0.f;
    for (int sl = 0; sl < 32; sl++) s += g_xmp[(size_t)(bd3*32+sl)*128 + o];
    g_xm[bd3*128 + o] = s * (1.f/2048.f);
}

__global__ void k_bcast()
{
    int t = blockIdx.x*blockDim.x + threadIdx.x;
    if (t >= BN_ALL*384) return;
    int bn = t / 384, r = t - bn*384;
    int d = r >> 7, o = r & 127;
    int b = bn / NPTS;
    g_xcat256[((size_t)bn*3 + d)*256 + 128 + o] = g_xm[(b*3+d)*128 + o];
}

// bias for i1 from xm constant half of xcat256
__global__ void k_bias_i1(const float* __restrict__ wi1f, const float* __restrict__ wi1d)
{
    int t = blockIdx.x*blockDim.x + threadIdx.x;
    if (t >= BATCH*3*256) return;
    int bd3 = t >> 8, r = t & 255;
    const float* wrow = (r < 128) ? (wi1f + r*256) : (wi1d + (r-128)*256);
    float s = 0.f;
    for (int c = 0; c < 128; c++) s = fmaf(wrow[128+c], g_xm[bd3*128 + c], s);
    g_bias[bd3*256 + r] = s;
}

// ------------------------- plain p/q LNA (G=2 GEMM output) ------------------
__global__ void k_lna_pd(int O, int osel)
{
    int t = blockIdx.x*blockDim.x + threadIdx.x;
    if (t >= BN_ALL*O) return;
    int bn = t / O, o = t - (t/O)*O;
    const float* Yb = g_Y + (size_t)bn*6*O;
    float p0=Yb[0*O+o], p1=Yb[1*O+o], p2=Yb[2*O+o];
    float q0=Yb[3*O+o], q1=Yb[4*O+o], q2=Yb[5*O+o];
    float o0,o1,o2; lna3(p0,p1,p2,q0,q1,q2,o0,o1,o2);
    if (osel == 0){
        float* out = g_t128 + (size_t)bn*3*128 + o;
        out[0]=o0; out[128]=o1; out[256]=o2;
    } else {
        float* out = g_x0v + (size_t)bn*3*256 + o;
        out[0]=o0; out[256]=o1; out[512]=o2;
    }
}

// ------------------------- final invariant ----------------------------------
__global__ void __launch_bounds__(256) k_inv(float* __restrict__ out)
{
    __shared__ float tile[256*33];
    int n0 = blockIdx.x * 32;          // global bn tile (never crosses batch)
    int t  = threadIdx.x;              // o = t
    for (int p = 0; p < 32; p++){
        size_t base = (size_t)(n0 + p)*3*256;
        float s = g_xcat256[base       + t]*g_x0v[base       + t]
                + g_xcat256[base + 256 + t]*g_x0v[base + 256 + t]
                + g_xcat256[base + 512 + t]*g_x0v[base + 512 + t];
        tile[t*33 + p] = s;
    }
    __syncthreads();
    int b   = n0 / NPTS;
    int nn0 = n0 - b*NPTS;
    int p   = t & 31, og = t >> 5;     // 8 o-groups
    for (int o = og; o < 256; o += 8)
        out[(size_t)(b*256 + o)*NPTS + nn0 + p] = tile[o*33 + p];
}

// ------------------------- launcher -----------------------------------------
extern "C" void kernel_launch(void* const* d_in, const int* in_sizes, int n_in,
                              void* d_out, int out_size)
{
    const float* x    = (const float*)d_in[0];
    const float* w1f  = (const float*)d_in[1];
    const float* w1d  = (const float*)d_in[2];
    const float* w2f  = (const float*)d_in[3];
    const float* w2d  = (const float*)d_in[4];
    const float* w3f  = (const float*)d_in[5];
    const float* w3d  = (const float*)d_in[6];
    const float* w4f  = (const float*)d_in[7];
    const float* w4d  = (const float*)d_in[8];
    const float* wcf  = (const float*)d_in[9];
    const float* wcd  = (const float*)d_in[10];
    const float* wi1f = (const float*)d_in[11];
    const float* wi1d = (const float*)d_in[12];
    const float* wi2f = (const float*)d_in[13];
    const float* wi2d = (const float*)d_in[14];
    float* out = (float*)d_out;

    k_prep<<<(BN_ALL+127)/128, 128>>>(x);
    k_knn_part<<<(BN_ALL*4+127)/128, 128>>>();
    k_knn_merge<<<(BN_ALL+127)/128, 128>>>();

    // ---- layer 1 (C=1 -> O=16)
    k_layer1<<<(BN_ALL*16+255)/256, 256>>>(w1f, w1d);
    k_gather<16,16><<<BN_ALL/16, 256>>>(0);

    // ---- layer 2 (C=16 -> O=32)
    k_wcomb_graph<<<(4*32*16+255)/256, 256>>>(w2f, w2d, 16, 32);
    k_gemm<<<dim3(M_COLS/128, 128/128), 256>>>(0, 0, 128, 16, 240, 0, 4, 32);
    k_gather<32,8><<<BN_ALL/8, 256>>>(16);

    // ---- layer 3 (C=32 -> O=64)
    k_wcomb_graph<<<(4*64*32+255)/256, 256>>>(w3f, w3d, 32, 64);
    k_gemm<<<dim3(M_COLS/128, 256/128), 256>>>(0, 0, 256, 32, 240, 16, 4, 64);
    k_gather<64,4><<<BN_ALL/4, 256>>>(48);

    // ---- layer 4 (C=64 -> O=128)
    k_wcomb_graph<<<(4*128*64+255)/256, 256>>>(w4f, w4d, 64, 128);
    k_gemm<<<dim3(M_COLS/128, 512/128), 256>>>(0, 0, 512, 64, 240, 48, 4, 128);
    k_gather<128,2><<<BN_ALL/2, 256>>>(112);

    // ---- concat layer (wcf 128x240, wcd 1x240)
    k_wcomb_c<<<(128*240+255)/256, 256>>>(wcf);
    k_gemm<<<dim3(M_COLS/128, 128/128), 256>>>(0, 0, 128, 240, 240, 0, 1, 128);
    k_dc<<<(M_COLS*32+255)/256, 256>>>(wcd);
    k_lna_c<<<(BN_ALL*128+255)/256, 256>>>();

    // ---- xm mean over N + broadcast into channels [128,256)
    k_xm_part<<<BATCH*3*32, 128>>>();
    k_xm_final<<<(BATCH*3*128+255)/256, 256>>>();
    k_bcast<<<(BN_ALL*384+255)/256, 256>>>();

    // ---- i1 (wi1f/wi1d 128x256; contract 128 + xm bias)
    k_wcomb_i1<<<(256*128+255)/256, 256>>>(wi1f, wi1d);
    k_bias_i1<<<(BATCH*3*256+255)/256, 256>>>(wi1f, wi1d);
    k_gemm<<<dim3(M_COLS/128, 256/128), 256>>>(1, 1, 256, 128, 256, 0, 2, 128);
    k_lna_pd<<<(BN_ALL*128+255)/256, 256>>>(128, 0);

    // ---- i2 (wi2f/wi2d 256x128)
    k_wcomb_i2<<<(512*128+255)/256, 256>>>(wi2f, wi2d);
    k_gemm<<<dim3(M_COLS/128, 512/128), 256>>>(2, 0, 512, 128, 128, 0, 2, 256);
    k_lna_pd<<<(BN_ALL*256+255)/256, 256>>>(256, 1);

    // ---- invariant output (B,256,N)
    k_inv<<<BN_ALL/32, 256>>>(out);
}

// round 4
// speedup vs baseline: 1.2810x; 1.1217x over previous
#include <cuda_runtime.h>
#include <cuda_bf16.h>
#include <cstdint>

#define BATCH 4
#define NPTS  2048
#define KNN   16
#define BN_ALL (BATCH*NPTS)      // 8192
#define M_COLS (BN_ALL*3)        // 24576

// ------------------------- scratch (device globals; no mallocs) -------------
static __device__ __align__(16) float g_X0[BN_ALL*3];
static __device__ float g_sq[BN_ALL];
static __device__ int   g_idx[BN_ALL*KNN];
static __device__ float g_knnd[BN_ALL*64];
static __device__ int   g_knni[BN_ALL*64];
static __device__ __align__(16) float g_xcat240[BN_ALL*3*240];
static __device__ __align__(16) float g_xcat256[BN_ALL*3*256];
static __device__ __align__(16) float g_t128 [BN_ALL*3*128];
static __device__ __align__(16) float g_x0v  [BN_ALL*3*256];
static __device__ __align__(16) float g_Y    [BN_ALL*1536];   // reused per layer
static __device__ float g_dc  [M_COLS];
static __device__ float g_xm  [BATCH*3*128];
static __device__ float g_xmp [BATCH*3*32*128];
static __device__ float g_bias[BATCH*3*512];
static __device__ __align__(16) __nv_bfloat16 g_Wh[512*256];
static __device__ __align__(16) __nv_bfloat16 g_Wl[512*256];

// ------------------------- helpers ------------------------------------------
__device__ __forceinline__ void lna3(float p0,float p1,float p2,
                                     float q0,float q1,float q2,
                                     float&o0,float&o1,float&o2)
{
    float dot = p0*q0 + p1*q1 + p2*q2;
    float dsq = q0*q0 + q1*q1 + q2*q2;
    float s = (dot < 0.f) ? 0.8f*dot/(dsq + 1e-6f) : 0.f;
    o0 = p0 - s*q0; o1 = p1 - s*q1; o2 = p2 - s*q2;
}

__device__ __forceinline__ uint32_t cvt2bf(float x, float y, bool lo)
{
    __nv_bfloat16 hx = __float2bfloat16(x), hy = __float2bfloat16(y);
    if (lo){
        hx = __float2bfloat16(x - __bfloat162float(hx));
        hy = __float2bfloat16(y - __bfloat162float(hy));
    }
    __nv_bfloat162 p; p.x = hx; p.y = hy;
    return *(uint32_t*)&p;
}

// ------------------------- prep / KNN ----------------------------------------
__global__ void k_prep(const float* __restrict__ x)
{
    int i = blockIdx.x*blockDim.x + threadIdx.x;
    if (i >= BN_ALL) return;
    int b = i / NPTS, n = i - b*NPTS;
    float vx = x[(b*3+0)*NPTS + n];
    float vy = x[(b*3+1)*NPTS + n];
    float vz = x[(b*3+2)*NPTS + n];
    g_X0[i*3+0]=vx; g_X0[i*3+1]=vy; g_X0[i*3+2]=vz;
    g_sq[i] = fmaf(vz,vz, fmaf(vy,vy, vx*vx));
}

__global__ void k_knn_part()
{
    int t = blockIdx.x*blockDim.x + threadIdx.x;
    if (t >= BN_ALL*4) return;
    int bn    = t & (BN_ALL-1);
    int chunk = t >> 13;
    int b = bn / NPTS;
    float px = g_X0[bn*3], py = g_X0[bn*3+1], pz = g_X0[bn*3+2];
    float sn = g_sq[bn];
    const float* Xb = g_X0 + b*NPTS*3;
    const float* Sb = g_sq + b*NPTS;
    float bd[KNN]; int bi[KNN];
    #pragma unroll
    for (int i = 0; i < KNN; i++){ bd[i] = 3.4e38f; bi[i] = 0; }
    int m0 = chunk*512;
    for (int mm = 0; mm < 512; mm++){
        int m = m0 + mm;
        float qx = Xb[m*3], qy = Xb[m*3+1], qz = Xb[m*3+2];
        float dot = fmaf(pz,qz, fmaf(py,qy, px*qx));
        float d2  = (sn + Sb[m]) - 2.f*dot;
        if (d2 < bd[KNN-1]){
            int p = KNN-1;
            while (p > 0 && bd[p-1] > d2){ bd[p]=bd[p-1]; bi[p]=bi[p-1]; p--; }
            bd[p] = d2; bi[p] = m;
        }
    }
    for (int i = 0; i < KNN; i++){
        g_knnd[bn*64 + chunk*16 + i] = bd[i];
        g_knni[bn*64 + chunk*16 + i] = bi[i];
    }
}

__global__ void k_knn_merge()
{
    int bn = blockIdx.x*blockDim.x + threadIdx.x;
    if (bn >= BN_ALL) return;
    float bd[KNN]; int bi[KNN];
    #pragma unroll
    for (int i = 0; i < KNN; i++){ bd[i] = 3.4e38f; bi[i] = 0; }
    for (int e = 0; e < 64; e++){
        float d2 = g_knnd[bn*64 + e];
        int   m  = g_knni[bn*64 + e];
        if (d2 < bd[KNN-1]){
            int p = KNN-1;
            while (p > 0 && bd[p-1] > d2){ bd[p]=bd[p-1]; bi[p]=bi[p-1]; p--; }
            bd[p] = d2; bi[p] = m;
        }
    }
    for (int i = 0; i < KNN; i++) g_idx[bn*KNN + i] = bi[i];
}

// ------------------------- layer 1 direct Y build (C=1, O=16) ---------------
__global__ void k_layer1(const float* __restrict__ w1f, const float* __restrict__ w1d)
{
    int t = blockIdx.x*blockDim.x + threadIdx.x;
    if (t >= BN_ALL*16) return;
    int bn = t >> 4, o = t & 15;
    float x0 = g_X0[bn*3], x1 = g_X0[bn*3+1], x2 = g_X0[bn*3+2];
    float wf0 = w1f[o*2], wf1 = w1f[o*2+1];
    float wd0 = w1d[o*2], wd1 = w1d[o*2+1];
    float r[4] = { wf0, wf1 - wf0, wd0, wd1 - wd0 };
    float* Y = g_Y + (size_t)bn*192;
    #pragma unroll
    for (int g = 0; g < 4; g++){
        Y[(g*3+0)*16 + o] = r[g]*x0;
        Y[(g*3+1)*16 + o] = r[g]*x1;
        Y[(g*3+2)*16 + o] = r[g]*x2;
    }
}

// ------------------------- weight combiners (write bf16 hi/lo) --------------
__device__ __forceinline__ void split_store(size_t idx, float v)
{
    __nv_bfloat16 h = __float2bfloat16(v);
    g_Wh[idx] = h;
    g_Wl[idx] = __float2bfloat16(v - __bfloat162float(h));
}

__global__ void k_wcomb_graph(const float* __restrict__ Wf, const float* __restrict__ Wd,
                              int C, int O)
{
    int t = blockIdx.x*blockDim.x + threadIdx.x;
    if (t >= 4*O*C) return;
    int r = t / C, c = t - r*C;
    int g = r / O, o = r - g*O;
    float v;
    if      (g == 0) v = Wf[o*2*C + c];
    else if (g == 1) v = Wf[o*2*C + C + c] - Wf[o*2*C + c];
    else if (g == 2) v = Wd[o*2*C + c];
    else             v = Wd[o*2*C + C + c] - Wd[o*2*C + c];
    split_store((size_t)r*C + c, v);
}

__global__ void k_wcomb_c(const float* __restrict__ wcf)
{
    int t = blockIdx.x*blockDim.x + threadIdx.x;
    if (t < 128*240) split_store(t, wcf[t]);
}

__global__ void k_wcomb_i1(const float* __restrict__ wi1f, const float* __restrict__ wi1d)
{
    int t = blockIdx.x*blockDim.x + threadIdx.x;
    if (t >= 256*128) return;
    int r = t >> 7, c = t & 127;
    split_store(t, (r < 128) ? wi1f[r*256 + c] : wi1d[(r-128)*256 + c]);
}

__global__ void k_wcomb_i2(const float* __restrict__ wi2f, const float* __restrict__ wi2d)
{
    int t = blockIdx.x*blockDim.x + threadIdx.x;
    if (t >= 512*128) return;
    int r = t >> 7, c = t & 127;
    split_store(t, (r < 256) ? wi2f[r*128 + c] : wi2d[(r-256)*128 + c]);
}

// ------------------------- warp-MMA GEMM (mma.sync bf16) --------------------
// Out[r][m] = sum_c W[r][c]*X[m][c] via bf16 split: [Whi|Wlo|Whi]·[Xhi|Xhi|Xlo]
// CTA tile 128(r) x 128(m); 8 warps 2x4; warp tile 64x32; K chunks of 32.
// SW64 swizzle: chunk' = chunk ^ ((row>>1)&3); rows are 64B.
#define SWZ(off) ((off) ^ (((off)>>3)&0x30))

__device__ __forceinline__ void ldsm_x4(uint32_t* a, uint32_t addr)
{
    asm volatile("ldmatrix.sync.aligned.m8n8.x4.shared.b16 {%0,%1,%2,%3}, [%4];"
        : "=r"(a[0]),"=r"(a[1]),"=r"(a[2]),"=r"(a[3]) : "r"(addr));
}
__device__ __forceinline__ void ldsm_x2(uint32_t* b, uint32_t addr)
{
    asm volatile("ldmatrix.sync.aligned.m8n8.x2.shared.b16 {%0,%1}, [%2];"
        : "=r"(b[0]),"=r"(b[1]) : "r"(addr));
}
__device__ __forceinline__ void mma16816(float* d, const uint32_t* a, const uint32_t* b)
{
    asm volatile("mma.sync.aligned.m16n8k16.row.col.f32.bf16.bf16.f32 "
        "{%0,%1,%2,%3}, {%4,%5,%6,%7}, {%8,%9}, {%0,%1,%2,%3};"
        : "+f"(d[0]),"+f"(d[1]),"+f"(d[2]),"+f"(d[3])
        : "r"(a[0]),"r"(a[1]),"r"(a[2]),"r"(a[3]),"r"(b[0]),"r"(b[1]));
}

__global__ void __launch_bounds__(256) k_hgemm(int xsel, int useBias,
                                               int R, int C, int CS, int co,
                                               int G, int O)
{
    __shared__ __align__(16) char sA[2][128*64];   // 128 rows x 32 bf16
    __shared__ __align__(16) char sB[2][128*64];
    const float* __restrict__ X = (xsel==0) ? g_xcat240 : (xsel==1) ? g_xcat256 : g_t128;

    int tid  = threadIdx.x, lane = tid & 31, warp = tid >> 5;
    int m0   = blockIdx.x*128, r0 = blockIdx.y*128;
    int nch  = (C + 31) >> 5;
    int EXT  = 3*nch;
    int wr   = (warp >> 2)*64;    // r offset within tile
    int wm   = (warp & 3)*32;     // m offset within tile

    int srow = tid >> 1, shalf = tid & 1;

    float acc[4][4][4];
    #pragma unroll
    for (int i=0;i<4;i++)
        #pragma unroll
        for (int j=0;j<4;j++)
            #pragma unroll
            for (int k=0;k<4;k++) acc[i][j][k]=0.f;

    uint4 aS0, aS1, bS0, bS1;

    // ---- staging: fetch ext-chunk e into registers
    auto stage = [&](int e){
        int term = e / nch, cblk = e - term*nch;
        bool valid = (cblk*32 + shalf*16) < C;
        const uint4 z = {0,0,0,0};
        if (valid){
            const __nv_bfloat16* Wsrc = (term == 1) ? g_Wl : g_Wh;
            const uint4* p = (const uint4*)&Wsrc[(size_t)(r0+srow)*C + cblk*32 + shalf*16];
            aS0 = p[0]; aS1 = p[1];
            bool lo = (term == 2);
            const float4* q = (const float4*)&X[(size_t)(m0+srow)*CS + co + cblk*32 + shalf*16];
            float4 f0=q[0], f1=q[1], f2=q[2], f3=q[3];
            bS0.x = cvt2bf(f0.x,f0.y,lo); bS0.y = cvt2bf(f0.z,f0.w,lo);
            bS0.z = cvt2bf(f1.x,f1.y,lo); bS0.w = cvt2bf(f1.z,f1.w,lo);
            bS1.x = cvt2bf(f2.x,f2.y,lo); bS1.y = cvt2bf(f2.z,f2.w,lo);
            bS1.z = cvt2bf(f3.x,f3.y,lo); bS1.w = cvt2bf(f3.z,f3.w,lo);
        } else { aS0=aS1=bS0=bS1=z; }
    };
    auto commit = [&](int buf){
        uint32_t o0 = SWZ((uint32_t)(srow*64 + (shalf*2  )*16));
        uint32_t o1 = SWZ((uint32_t)(srow*64 + (shalf*2+1)*16));
        *(uint4*)(sA[buf]+o0) = aS0;  *(uint4*)(sA[buf]+o1) = aS1;
        *(uint4*)(sB[buf]+o0) = bS0;  *(uint4*)(sB[buf]+o1) = bS1;
    };

    stage(0); commit(0); __syncthreads();

    for (int e = 0; e < EXT; e++){
        if (e+1 < EXT) stage(e+1);
        int buf = e & 1;
        uint32_t baseA = (uint32_t)__cvta_generic_to_shared(sA[buf]);
        uint32_t baseB = (uint32_t)__cvta_generic_to_shared(sB[buf]);
        #pragma unroll
        for (int ks = 0; ks < 32; ks += 16){
            uint32_t a[4][4], b[4][2];
            #pragma unroll
            for (int i = 0; i < 4; i++){
                uint32_t off = (uint32_t)((wr + i*16 + (lane & 15))*64 + ks*2 + (lane >> 4)*16);
                ldsm_x4(a[i], baseA + SWZ(off));
            }
            #pragma unroll
            for (int j = 0; j < 4; j++){
                uint32_t off = (uint32_t)((wm + j*8 + (lane & 7))*64 + ks*2 + ((lane >> 3) & 1)*16);
                ldsm_x2(b[j], baseB + SWZ(off));
            }
            #pragma unroll
            for (int i = 0; i < 4; i++)
                #pragma unroll
                for (int j = 0; j < 4; j++)
                    mma16816(acc[i][j], a[i], b[j]);
        }
        if (e+1 < EXT) commit((e+1) & 1);
        __syncthreads();
    }

    // ---- epilogue: scatter to g_Y layout
    #pragma unroll
    for (int i = 0; i < 4; i++){
        #pragma unroll
        for (int rh = 0; rh < 2; rh++){
            int r = r0 + wr + i*16 + (lane >> 2) + rh*8;
            int g = r / O, o = r - g*O;
            #pragma unroll
            for (int j = 0; j < 4; j++){
                #pragma unroll
                for (int c = 0; c < 2; c++){
                    int m  = m0 + wm + j*8 + (lane & 3)*2 + c;
                    int bn = m / 3, d = m - bn*3;
                    float v = acc[i][j][rh*2 + c];
                    if (useBias) v += g_bias[((bn/NPTS)*3 + d)*R + r];
                    g_Y[(size_t)((bn*G + g)*3 + d)*O + o] = v;
                }
            }
        }
    }
}

// ------------------------- gather + vec-LNA + mean over K -------------------
template<int O, int PPB>
__global__ void __launch_bounds__(256) k_gather(int co)
{
    __shared__ int sidx[PPB*KNN];
    int t  = threadIdx.x;
    int p0 = blockIdx.x * PPB;
    if (t < PPB*KNN) sidx[t] = g_idx[p0*KNN + t];
    __syncthreads();

    int pl = t / O;
    int o  = t - pl*O;
    int bn = p0 + pl;
    int jbase = (bn / NPTS) * NPTS;

    const float* Z = g_Y + (size_t)bn*12*O;
    float zp0=Z[(3+0)*O+o], zp1=Z[(3+1)*O+o], zp2=Z[(3+2)*O+o];
    float zq0=Z[(9+0)*O+o], zq1=Z[(9+1)*O+o], zq2=Z[(9+2)*O+o];
    float a0=0.f, a1=0.f, a2=0.f;

    #pragma unroll 4
    for (int k = 0; k < KNN; k++){
        int j = jbase + sidx[pl*KNN + k];
        const float* Yj = g_Y + (size_t)j*12*O;
        float p0v = Yj[0*O+o] + zp0;
        float p1v = Yj[1*O+o] + zp1;
        float p2v = Yj[2*O+o] + zp2;
        float q0  = Yj[6*O+o] + zq0;
        float q1  = Yj[7*O+o] + zq1;
        float q2  = Yj[8*O+o] + zq2;
        float dot = p0v*q0 + p1v*q1 + p2v*q2;
        float dsq = q0*q0 + q1*q1 + q2*q2;
        float s = (dot < 0.f) ? 0.8f*dot/(dsq + 1e-6f) : 0.f;
        a0 += p0v - s*q0; a1 += p1v - s*q1; a2 += p2v - s*q2;
    }
    float* out = g_xcat240 + (size_t)bn*3*240 + co + o;
    out[0]   = a0*0.0625f;
    out[240] = a1*0.0625f;
    out[480] = a2*0.0625f;
}

// ------------------------- layer c: dc GEMV (1x240) -------------------------
__global__ void k_dc(const float* __restrict__ wcd)
{
    int gt = blockIdx.x*blockDim.x + threadIdx.x;
    int warp = gt >> 5, lane = gt & 31;
    if (warp >= M_COLS) return;
    const float* row = g_xcat240 + (size_t)warp*240;
    float s = 0.f;
    for (int c = lane; c < 240; c += 32) s = fmaf(row[c], wcd[c], s);
    #pragma unroll
    for (int off = 16; off; off >>= 1) s += __shfl_xor_sync(0xffffffffu, s, off);
    if (lane == 0) g_dc[warp] = s;
}

__global__ void k_lna_c()
{
    int t = blockIdx.x*blockDim.x + threadIdx.x;
    if (t >= BN_ALL*128) return;
    int bn = t >> 7, o = t & 127;
    const float* Yb = g_Y + (size_t)bn*384;
    float p0 = Yb[0*128+o], p1 = Yb[1*128+o], p2 = Yb[2*128+o];
    float q0 = g_dc[bn*3+0], q1 = g_dc[bn*3+1], q2 = g_dc[bn*3+2];
    float o0,o1,o2; lna3(p0,p1,p2,q0,q1,q2,o0,o1,o2);
    float* out = g_xcat256 + (size_t)bn*3*256 + o;
    out[0] = o0; out[256] = o1; out[512] = o2;
}

// ------------------------- xm mean + broadcast ------------------------------
__global__ void k_xm_part()
{
    int blk  = blockIdx.x;
    int slab = blk & 31;
    int bd3  = blk >> 5;
    int b = bd3 / 3, d = bd3 - b*3;
    int o = threadIdx.x;
    float s = 0.f;
    for (int nn = 0; nn < 64; nn++){
        int n = slab*64 + nn;
        s += g_xcat256[((size_t)(b*NPTS+n)*3 + d)*256 + o];
    }
    g_xmp[(size_t)(bd3*32 + slab)*128 + o] = s;
}

__global__ void k_xm_final()
{
    int t = blockIdx.x*blockDim.x + threadIdx.x;
    if (t >= BATCH*3*128) return;
    int bd3 = t >> 7, o = t & 127;
    float s = 0.f;
    for (int sl = 0; sl < 32; sl++) s += g_xmp[(size_t)(bd3*32+sl)*128 + o];
    g_xm[bd3*128 + o] = s * (1.f/2048.f);
}

__global__ void k_bcast()
{
    int t = blockIdx.x*blockDim.x + threadIdx.x;
    if (t >= BN_ALL*384) return;
    int bn = t / 384, r = t - bn*384;
    int d = r >> 7, o = r & 127;
    int b = bn / NPTS;
    g_xcat256[((size_t)bn*3 + d)*256 + 128 + o] = g_xm[(b*3+d)*128 + o];
}

__global__ void k_bias_i1(const float* __restrict__ wi1f, const float* __restrict__ wi1d)
{
    int t = blockIdx.x*blockDim.x + threadIdx.x;
    if (t >= BATCH*3*256) return;
    int bd3 = t >> 8, r = t & 255;
    const float* wrow = (r < 128) ? (wi1f + r*256) : (wi1d + (r-128)*256);
    float s = 0.f;
    for (int c = 0; c < 128; c++) s = fmaf(wrow[128+c], g_xm[bd3*128 + c], s);
    g_bias[bd3*256 + r] = s;
}

// ------------------------- plain p/q LNA (G=2 GEMM output) ------------------
__global__ void k_lna_pd(int O, int osel)
{
    int t = blockIdx.x*blockDim.x + threadIdx.x;
    if (t >= BN_ALL*O) return;
    int bn = t / O, o = t - (t/O)*O;
    const float* Yb = g_Y + (size_t)bn*6*O;
    float p0=Yb[0*O+o], p1=Yb[1*O+o], p2=Yb[2*O+o];
    float q0=Yb[3*O+o], q1=Yb[4*O+o], q2=Yb[5*O+o];
    float o0,o1,o2; lna3(p0,p1,p2,q0,q1,q2,o0,o1,o2);
    if (osel == 0){
        float* out = g_t128 + (size_t)bn*3*128 + o;
        out[0]=o0; out[128]=o1; out[256]=o2;
    } else {
        float* out = g_x0v + (size_t)bn*3*256 + o;
        out[0]=o0; out[256]=o1; out[512]=o2;
    }
}

// ------------------------- final invariant ----------------------------------
__global__ void __launch_bounds__(256) k_inv(float* __restrict__ out)
{
    __shared__ float tile[256*33];
    int n0 = blockIdx.x * 32;
    int t  = threadIdx.x;
    for (int p = 0; p < 32; p++){
        size_t base = (size_t)(n0 + p)*3*256;
        float s = g_xcat256[base       + t]*g_x0v[base       + t]
                + g_xcat256[base + 256 + t]*g_x0v[base + 256 + t]
                + g_xcat256[base + 512 + t]*g_x0v[base + 512 + t];
        tile[t*33 + p] = s;
    }
    __syncthreads();
    int b   = n0 / NPTS;
    int nn0 = n0 - b*NPTS;
    int p   = t & 31, og = t >> 5;
    for (int o = og; o < 256; o += 8)
        out[(size_t)(b*256 + o)*NPTS + nn0 + p] = tile[o*33 + p];
}

// ------------------------- launcher -----------------------------------------
extern "C" void kernel_launch(void* const* d_in, const int* in_sizes, int n_in,
                              void* d_out, int out_size)
{
    const float* x    = (const float*)d_in[0];
    const float* w1f  = (const float*)d_in[1];
    const float* w1d  = (const float*)d_in[2];
    const float* w2f  = (const float*)d_in[3];
    const float* w2d  = (const float*)d_in[4];
    const float* w3f  = (const float*)d_in[5];
    const float* w3d  = (const float*)d_in[6];
    const float* w4f  = (const float*)d_in[7];
    const float* w4d  = (const float*)d_in[8];
    const float* wcf  = (const float*)d_in[9];
    const float* wcd  = (const float*)d_in[10];
    const float* wi1f = (const float*)d_in[11];
    const float* wi1d = (const float*)d_in[12];
    const float* wi2f = (const float*)d_in[13];
    const float* wi2d = (const float*)d_in[14];
    float* out = (float*)d_out;

    k_prep<<<(BN_ALL+127)/128, 128>>>(x);
    k_knn_part<<<(BN_ALL*4+127)/128, 128>>>();
    k_knn_merge<<<(BN_ALL+127)/128, 128>>>();

    // ---- layer 1 (C=1 -> O=16)
    k_layer1<<<(BN_ALL*16+255)/256, 256>>>(w1f, w1d);
    k_gather<16,16><<<BN_ALL/16, 256>>>(0);

    // ---- layer 2 (C=16 -> O=32)
    k_wcomb_graph<<<(4*32*16+255)/256, 256>>>(w2f, w2d, 16, 32);
    k_hgemm<<<dim3(M_COLS/128, 1), 256>>>(0, 0, 128, 16, 240, 0, 4, 32);
    k_gather<32,8><<<BN_ALL/8, 256>>>(16);

    // ---- layer 3 (C=32 -> O=64)
    k_wcomb_graph<<<(4*64*32+255)/256, 256>>>(w3f, w3d, 32, 64);
    k_hgemm<<<dim3(M_COLS/128, 2), 256>>>(0, 0, 256, 32, 240, 16, 4, 64);
    k_gather<64,4><<<BN_ALL/4, 256>>>(48);

    // ---- layer 4 (C=64 -> O=128)
    k_wcomb_graph<<<(4*128*64+255)/256, 256>>>(w4f, w4d, 64, 128);
    k_hgemm<<<dim3(M_COLS/128, 4), 256>>>(0, 0, 512, 64, 240, 48, 4, 128);
    k_gather<128,2><<<BN_ALL/2, 256>>>(112);

    // ---- concat layer (wcf 128x240, wcd 1x240)
    k_wcomb_c<<<(128*240+255)/256, 256>>>(wcf);
    k_hgemm<<<dim3(M_COLS/128, 1), 256>>>(0, 0, 128, 240, 240, 0, 1, 128);
    k_dc<<<(M_COLS*32+255)/256, 256>>>(wcd);
    k_lna_c<<<(BN_ALL*128+255)/256, 256>>>();

    // ---- xm mean over N + broadcast into channels [128,256)
    k_xm_part<<<BATCH*3*32, 128>>>();
    k_xm_final<<<(BATCH*3*128+255)/256, 256>>>();
    k_bcast<<<(BN_ALL*384+255)/256, 256>>>();

    // ---- i1 (wi1f/wi1d 128x256; contract 128 + xm bias)
    k_wcomb_i1<<<(256*128+255)/256, 256>>>(wi1f, wi1d);
    k_bias_i1<<<(BATCH*3*256+255)/256, 256>>>(wi1f, wi1d);
    k_hgemm<<<dim3(M_COLS/128, 2), 256>>>(1, 1, 256, 128, 256, 0, 2, 128);
    k_lna_pd<<<(BN_ALL*128+255)/256, 256>>>(128, 0);

    // ---- i2 (wi2f/wi2d 256x128)
    k_wcomb_i2<<<(512*128+255)/256, 256>>>(wi2f, wi2d);
    k_hgemm<<<dim3(M_COLS/128, 4), 256>>>(2, 0, 512, 128, 128, 0, 2, 256);
    k_lna_pd<<<(BN_ALL*256+255)/256, 256>>>(256, 1);

    // ---- invariant output (B,256,N)
    k_inv<<<BN_ALL/32, 256>>>(out);
}

// round 5
// speedup vs baseline: 1.3590x; 1.0608x over previous
#include <cuda_runtime.h>
#include <cuda_bf16.h>
#include <cstdint>

#define BATCH 4
#define NPTS  2048
#define KNN   16
#define BN_ALL (BATCH*NPTS)      // 8192
#define M_COLS (BN_ALL*3)        // 24576

// ------------------------- scratch (device globals; no mallocs) -------------
static __device__ __align__(16) float g_X0[BN_ALL*3];
static __device__ float g_sq[BN_ALL];
static __device__ int   g_idx[BN_ALL*KNN];
static __device__ float g_knnd[BN_ALL*64];
static __device__ int   g_knni[BN_ALL*64];
static __device__ __align__(16) float g_xcat240[BN_ALL*3*240];
static __device__ __align__(16) float g_xcat256[BN_ALL*3*256];
static __device__ __align__(16) float g_t128 [BN_ALL*3*128];
static __device__ __align__(16) float g_x0v  [BN_ALL*3*256];
static __device__ __align__(16) float g_Y    [BN_ALL*1536];   // reused per layer
static __device__ float g_dc  [M_COLS];
static __device__ float g_xm  [BATCH*3*128];
static __device__ float g_xmp [BATCH*3*32*128];
static __device__ float g_bias[BATCH*3*512];
static __device__ __align__(16) __nv_bfloat16 g_Wh[512*256];
static __device__ __align__(16) __nv_bfloat16 g_Wl[512*256];

// ------------------------- helpers ------------------------------------------
__device__ __forceinline__ void lna3(float p0,float p1,float p2,
                                     float q0,float q1,float q2,
                                     float&o0,float&o1,float&o2)
{
    float dot = p0*q0 + p1*q1 + p2*q2;
    float dsq = q0*q0 + q1*q1 + q2*q2;
    float s = (dot < 0.f) ? 0.8f*dot/(dsq + 1e-6f) : 0.f;
    o0 = p0 - s*q0; o1 = p1 - s*q1; o2 = p2 - s*q2;
}

__device__ __forceinline__ uint32_t cvt2bf(float x, float y, bool lo)
{
    __nv_bfloat16 hx = __float2bfloat16(x), hy = __float2bfloat16(y);
    if (lo){
        hx = __float2bfloat16(x - __bfloat162float(hx));
        hy = __float2bfloat16(y - __bfloat162float(hy));
    }
    __nv_bfloat162 p; p.x = hx; p.y = hy;
    return *(uint32_t*)&p;
}

// ------------------------- prep / KNN ----------------------------------------
__global__ void k_prep(const float* __restrict__ x)
{
    int i = blockIdx.x*blockDim.x + threadIdx.x;
    if (i >= BN_ALL) return;
    int b = i / NPTS, n = i - b*NPTS;
    float vx = x[(b*3+0)*NPTS + n];
    float vy = x[(b*3+1)*NPTS + n];
    float vz = x[(b*3+2)*NPTS + n];
    g_X0[i*3+0]=vx; g_X0[i*3+1]=vy; g_X0[i*3+2]=vz;
    g_sq[i] = fmaf(vz,vz, fmaf(vy,vy, vx*vx));
}

__global__ void k_knn_part()
{
    int t = blockIdx.x*blockDim.x + threadIdx.x;
    if (t >= BN_ALL*4) return;
    int bn    = t & (BN_ALL-1);
    int chunk = t >> 13;
    int b = bn / NPTS;
    float px = g_X0[bn*3], py = g_X0[bn*3+1], pz = g_X0[bn*3+2];
    float sn = g_sq[bn];
    const float* Xb = g_X0 + b*NPTS*3;
    const float* Sb = g_sq + b*NPTS;
    float bd[KNN]; int bi[KNN];
    #pragma unroll
    for (int i = 0; i < KNN; i++){ bd[i] = 3.4e38f; bi[i] = 0; }
    int m0 = chunk*512;
    #pragma unroll 4
    for (int mm = 0; mm < 512; mm++){
        int m = m0 + mm;
        float qx = Xb[m*3], qy = Xb[m*3+1], qz = Xb[m*3+2];
        float dot = fmaf(pz,qz, fmaf(py,qy, px*qx));
        float d2  = (sn + Sb[m]) - 2.f*dot;
        if (d2 < bd[KNN-1]){
            int p = KNN-1;
            while (p > 0 && bd[p-1] > d2){ bd[p]=bd[p-1]; bi[p]=bi[p-1]; p--; }
            bd[p] = d2; bi[p] = m;
        }
    }
    for (int i = 0; i < KNN; i++){
        g_knnd[bn*64 + chunk*16 + i] = bd[i];
        g_knni[bn*64 + chunk*16 + i] = bi[i];
    }
}

__global__ void k_knn_merge()
{
    int bn = blockIdx.x*blockDim.x + threadIdx.x;
    if (bn >= BN_ALL) return;
    float bd[KNN]; int bi[KNN];
    #pragma unroll
    for (int i = 0; i < KNN; i++){ bd[i] = 3.4e38f; bi[i] = 0; }
    for (int e = 0; e < 64; e++){
        float d2 = g_knnd[bn*64 + e];
        int   m  = g_knni[bn*64 + e];
        if (d2 < bd[KNN-1]){
            int p = KNN-1;
            while (p > 0 && bd[p-1] > d2){ bd[p]=bd[p-1]; bi[p]=bi[p-1]; p--; }
            bd[p] = d2; bi[p] = m;
        }
    }
    for (int i = 0; i < KNN; i++) g_idx[bn*KNN + i] = bi[i];
}

// ------------------------- layer 1 direct Y build (C=1, O=16), vec4 ---------
__global__ void k_layer1(const float* __restrict__ w1f, const float* __restrict__ w1d)
{
    int t = blockIdx.x*blockDim.x + threadIdx.x;
    if (t >= BN_ALL*48) return;
    int bn = t / 48, r = t - bn*48;
    int pl = r >> 2, o4 = (r & 3)*4;
    int g = pl / 3, d = pl - g*3;
    float xv = g_X0[bn*3 + d];
    const float* W = (g < 2) ? w1f : w1d;
    float4 wa = *(const float4*)&W[o4*2];
    float4 wb = *(const float4*)&W[o4*2 + 4];
    float4 out;
    if ((g & 1) == 0){
        out.x = wa.x*xv; out.y = wa.z*xv; out.z = wb.x*xv; out.w = wb.z*xv;
    } else {
        out.x = (wa.y-wa.x)*xv; out.y = (wa.w-wa.z)*xv;
        out.z = (wb.y-wb.x)*xv; out.w = (wb.w-wb.z)*xv;
    }
    *(float4*)&g_Y[(size_t)bn*192 + pl*16 + o4] = out;
}

// ------------------------- weight combiners (write bf16 hi/lo) --------------
__device__ __forceinline__ void split_store(size_t idx, float v)
{
    __nv_bfloat16 h = __float2bfloat16(v);
    g_Wh[idx] = h;
    g_Wl[idx] = __float2bfloat16(v - __bfloat162float(h));
}

__global__ void k_wcomb_graph(const float* __restrict__ Wf, const float* __restrict__ Wd,
                              int C, int O)
{
    int t = blockIdx.x*blockDim.x + threadIdx.x;
    if (t >= 4*O*C) return;
    int r = t / C, c = t - r*C;
    int g = r / O, o = r - g*O;
    float v;
    if      (g == 0) v = Wf[o*2*C + c];
    else if (g == 1) v = Wf[o*2*C + C + c] - Wf[o*2*C + c];
    else if (g == 2) v = Wd[o*2*C + c];
    else             v = Wd[o*2*C + C + c] - Wd[o*2*C + c];
    split_store((size_t)r*C + c, v);
}

__global__ void k_wcomb_c(const float* __restrict__ wcf)
{
    int t = blockIdx.x*blockDim.x + threadIdx.x;
    if (t < 128*240) split_store(t, wcf[t]);
}

__global__ void k_wcomb_i1(const float* __restrict__ wi1f, const float* __restrict__ wi1d)
{
    int t = blockIdx.x*blockDim.x + threadIdx.x;
    if (t >= 256*128) return;
    int r = t >> 7, c = t & 127;
    split_store(t, (r < 128) ? wi1f[r*256 + c] : wi1d[(r-128)*256 + c]);
}

__global__ void k_wcomb_i2(const float* __restrict__ wi2f, const float* __restrict__ wi2d)
{
    int t = blockIdx.x*blockDim.x + threadIdx.x;
    if (t >= 512*128) return;
    int r = t >> 7, c = t & 127;
    split_store(t, (r < 256) ? wi2f[r*128 + c] : wi2d[(r-256)*128 + c]);
}

// ------------------------- warp-MMA GEMM (mma.sync bf16) --------------------
#define SWZ(off) ((off) ^ (((off)>>3)&0x30))

__device__ __forceinline__ void ldsm_x4(uint32_t* a, uint32_t addr)
{
    asm volatile("ldmatrix.sync.aligned.m8n8.x4.shared.b16 {%0,%1,%2,%3}, [%4];"
        : "=r"(a[0]),"=r"(a[1]),"=r"(a[2]),"=r"(a[3]) : "r"(addr));
}
__device__ __forceinline__ void ldsm_x2(uint32_t* b, uint32_t addr)
{
    asm volatile("ldmatrix.sync.aligned.m8n8.x2.shared.b16 {%0,%1}, [%2];"
        : "=r"(b[0]),"=r"(b[1]) : "r"(addr));
}
__device__ __forceinline__ void mma16816(float* d, const uint32_t* a, const uint32_t* b)
{
    asm volatile("mma.sync.aligned.m16n8k16.row.col.f32.bf16.bf16.f32 "
        "{%0,%1,%2,%3}, {%4,%5,%6,%7}, {%8,%9}, {%0,%1,%2,%3};"
        : "+f"(d[0]),"+f"(d[1]),"+f"(d[2]),"+f"(d[3])
        : "r"(a[0]),"r"(a[1]),"r"(a[2]),"r"(a[3]),"r"(b[0]),"r"(b[1]));
}

__global__ void __launch_bounds__(256) k_hgemm(int xsel, int useBias,
                                               int R, int C, int CS, int co,
                                               int G, int O)
{
    __shared__ __align__(16) char sA[2][128*64];
    __shared__ __align__(16) char sB[2][128*64];
    const float* __restrict__ X = (xsel==0) ? g_xcat240 : (xsel==1) ? g_xcat256 : g_t128;

    int tid  = threadIdx.x, lane = tid & 31, warp = tid >> 5;
    int m0   = blockIdx.x*128, r0 = blockIdx.y*128;
    int nch  = (C + 31) >> 5;
    int EXT  = 3*nch;
    int wr   = (warp >> 2)*64;
    int wm   = (warp & 3)*32;

    int srow = tid >> 1, shalf = tid & 1;

    float acc[4][4][4];
    #pragma unroll
    for (int i=0;i<4;i++)
        #pragma unroll
        for (int j=0;j<4;j++)
            #pragma unroll
            for (int k=0;k<4;k++) acc[i][j][k]=0.f;

    uint4 aS0, aS1, bS0, bS1;

    auto stage = [&](int e){
        int term = e / nch, cblk = e - term*nch;
        bool valid = (cblk*32 + shalf*16) < C;
        const uint4 z = {0,0,0,0};
        if (valid){
            const __nv_bfloat16* Wsrc = (term == 1) ? g_Wl : g_Wh;
            const uint4* p = (const uint4*)&Wsrc[(size_t)(r0+srow)*C + cblk*32 + shalf*16];
            aS0 = p[0]; aS1 = p[1];
            bool lo = (term == 2);
            const float4* q = (const float4*)&X[(size_t)(m0+srow)*CS + co + cblk*32 + shalf*16];
            float4 f0=q[0], f1=q[1], f2=q[2], f3=q[3];
            bS0.x = cvt2bf(f0.x,f0.y,lo); bS0.y = cvt2bf(f0.z,f0.w,lo);
            bS0.z = cvt2bf(f1.x,f1.y,lo); bS0.w = cvt2bf(f1.z,f1.w,lo);
            bS1.x = cvt2bf(f2.x,f2.y,lo); bS1.y = cvt2bf(f2.z,f2.w,lo);
            bS1.z = cvt2bf(f3.x,f3.y,lo); bS1.w = cvt2bf(f3.z,f3.w,lo);
        } else { aS0=aS1=bS0=bS1=z; }
    };
    auto commit = [&](int buf){
        uint32_t o0 = SWZ((uint32_t)(srow*64 + (shalf*2  )*16));
        uint32_t o1 = SWZ((uint32_t)(srow*64 + (shalf*2+1)*16));
        *(uint4*)(sA[buf]+o0) = aS0;  *(uint4*)(sA[buf]+o1) = aS1;
        *(uint4*)(sB[buf]+o0) = bS0;  *(uint4*)(sB[buf]+o1) = bS1;
    };

    stage(0); commit(0); __syncthreads();

    for (int e = 0; e < EXT; e++){
        if (e+1 < EXT) stage(e+1);
        int buf = e & 1;
        uint32_t baseA = (uint32_t)__cvta_generic_to_shared(sA[buf]);
        uint32_t baseB = (uint32_t)__cvta_generic_to_shared(sB[buf]);
        #pragma unroll
        for (int ks = 0; ks < 32; ks += 16){
            uint32_t a[4][4], b[4][2];
            #pragma unroll
            for (int i = 0; i < 4; i++){
                uint32_t off = (uint32_t)((wr + i*16 + (lane & 15))*64 + ks*2 + (lane >> 4)*16);
                ldsm_x4(a[i], baseA + SWZ(off));
            }
            #pragma unroll
            for (int j = 0; j < 4; j++){
                uint32_t off = (uint32_t)((wm + j*8 + (lane & 7))*64 + ks*2 + ((lane >> 3) & 1)*16);
                ldsm_x2(b[j], baseB + SWZ(off));
            }
            #pragma unroll
            for (int i = 0; i < 4; i++)
                #pragma unroll
                for (int j = 0; j < 4; j++)
                    mma16816(acc[i][j], a[i], b[j]);
        }
        if (e+1 < EXT) commit((e+1) & 1);
        __syncthreads();
    }

    #pragma unroll
    for (int i = 0; i < 4; i++){
        #pragma unroll
        for (int rh = 0; rh < 2; rh++){
            int r = r0 + wr + i*16 + (lane >> 2) + rh*8;
            int g = r / O, o = r - g*O;
            #pragma unroll
            for (int j = 0; j < 4; j++){
                #pragma unroll
                for (int c = 0; c < 2; c++){
                    int m  = m0 + wm + j*8 + (lane & 3)*2 + c;
                    int bn = m / 3, d = m - bn*3;
                    float v = acc[i][j][rh*2 + c];
                    if (useBias) v += g_bias[((bn/NPTS)*3 + d)*R + r];
                    g_Y[(size_t)((bn*G + g)*3 + d)*O + o] = v;
                }
            }
        }
    }
}

// ------------------------- gather + vec-LNA + mean over K (float4) ----------
template<int O, int PPB>
__global__ void __launch_bounds__(256) k_gather(int co)
{
    __shared__ int sidx[PPB*KNN];
    int t  = threadIdx.x;
    int p0 = blockIdx.x * PPB;
    for (int i = t; i < PPB*KNN; i += 256) sidx[i] = g_idx[p0*KNN + i];
    __syncthreads();

    constexpr int TPP = O/4;
    int pl = t / TPP;
    int oc = (t - pl*TPP)*4;
    int bn = p0 + pl;
    int jbase = (bn / NPTS) * NPTS;

    const float* Z = g_Y + (size_t)bn*12*O + oc;
    float4 zp0 = *(const float4*)(Z + 3*O);
    float4 zp1 = *(const float4*)(Z + 4*O);
    float4 zp2 = *(const float4*)(Z + 5*O);
    float4 zq0 = *(const float4*)(Z + 9*O);
    float4 zq1 = *(const float4*)(Z + 10*O);
    float4 zq2 = *(const float4*)(Z + 11*O);
    float a0[4] = {0,0,0,0}, a1[4] = {0,0,0,0}, a2[4] = {0,0,0,0};

    for (int k = 0; k < KNN; k++){
        int j = jbase + sidx[pl*KNN + k];
        const float* Yj = g_Y + (size_t)j*12*O + oc;
        float4 P0 = *(const float4*)(Yj + 0*O);
        float4 P1 = *(const float4*)(Yj + 1*O);
        float4 P2 = *(const float4*)(Yj + 2*O);
        float4 Q0 = *(const float4*)(Yj + 6*O);
        float4 Q1 = *(const float4*)(Yj + 7*O);
        float4 Q2 = *(const float4*)(Yj + 8*O);
        #pragma unroll
        for (int c = 0; c < 4; c++){
            float p0v = (&P0.x)[c] + (&zp0.x)[c];
            float p1v = (&P1.x)[c] + (&zp1.x)[c];
            float p2v = (&P2.x)[c] + (&zp2.x)[c];
            float q0  = (&Q0.x)[c] + (&zq0.x)[c];
            float q1  = (&Q1.x)[c] + (&zq1.x)[c];
            float q2  = (&Q2.x)[c] + (&zq2.x)[c];
            float dot = p0v*q0 + p1v*q1 + p2v*q2;
            float dsq = q0*q0 + q1*q1 + q2*q2;
            float s = (dot < 0.f) ? 0.8f*dot/(dsq + 1e-6f) : 0.f;
            a0[c] += p0v - s*q0; a1[c] += p1v - s*q1; a2[c] += p2v - s*q2;
        }
    }
    float* out = g_xcat240 + (size_t)bn*3*240 + co + oc;
    float4 v0 = {a0[0]*0.0625f, a0[1]*0.0625f, a0[2]*0.0625f, a0[3]*0.0625f};
    float4 v1 = {a1[0]*0.0625f, a1[1]*0.0625f, a1[2]*0.0625f, a1[3]*0.0625f};
    float4 v2 = {a2[0]*0.0625f, a2[1]*0.0625f, a2[2]*0.0625f, a2[3]*0.0625f};
    *(float4*)(out)       = v0;
    *(float4*)(out + 240) = v1;
    *(float4*)(out + 480) = v2;
}

// ------------------------- layer c: dc GEMV (1x240), vec4 --------------------
__global__ void k_dc(const float* __restrict__ wcd)
{
    int gt = blockIdx.x*blockDim.x + threadIdx.x;
    int warp = gt >> 5, lane = gt & 31;
    if (warp >= M_COLS) return;
    const float* row = g_xcat240 + (size_t)warp*240;
    float s = 0.f;
    for (int c = lane; c < 60; c += 32){
        float4 a = *(const float4*)&row[c*4];
        float4 w = *(const float4*)&wcd[c*4];
        s += a.x*w.x + a.y*w.y + a.z*w.z + a.w*w.w;
    }
    #pragma unroll
    for (int off = 16; off; off >>= 1) s += __shfl_xor_sync(0xffffffffu, s, off);
    if (lane == 0) g_dc[warp] = s;
}

// layer c LNA (q shared across o), vec4
__global__ void k_lna_c()
{
    int t = blockIdx.x*blockDim.x + threadIdx.x;
    if (t >= BN_ALL*32) return;
    int bn = t >> 5, oc = (t & 31)*4;
    const float* Yb = g_Y + (size_t)bn*384 + oc;
    float4 P0 = *(const float4*)(Yb);
    float4 P1 = *(const float4*)(Yb + 128);
    float4 P2 = *(const float4*)(Yb + 256);
    float q0 = g_dc[bn*3+0], q1 = g_dc[bn*3+1], q2 = g_dc[bn*3+2];
    float4 O0, O1, O2;
    #pragma unroll
    for (int c = 0; c < 4; c++){
        float o0,o1,o2;
        lna3((&P0.x)[c], (&P1.x)[c], (&P2.x)[c], q0, q1, q2, o0,o1,o2);
        (&O0.x)[c]=o0; (&O1.x)[c]=o1; (&O2.x)[c]=o2;
    }
    float* out = g_xcat256 + (size_t)bn*3*256 + oc;
    *(float4*)(out)       = O0;
    *(float4*)(out + 256) = O1;
    *(float4*)(out + 512) = O2;
}

// ------------------------- xm mean + broadcast ------------------------------
__global__ void k_xm_part()
{
    int blk  = blockIdx.x;
    int slab = blk & 31;
    int bd3  = blk >> 5;
    int b = bd3 / 3, d = bd3 - b*3;
    int o = threadIdx.x;
    float s = 0.f;
    for (int nn = 0; nn < 64; nn++){
        int n = slab*64 + nn;
        s += g_xcat256[((size_t)(b*NPTS+n)*3 + d)*256 + o];
    }
    g_xmp[(size_t)(bd3*32 + slab)*128 + o] = s;
}

__global__ void k_xm_final()
{
    int t = blockIdx.x*blockDim.x + threadIdx.x;
    if (t >= BATCH*3*128) return;
    int bd3 = t >> 7, o = t & 127;
    float s = 0.f;
    for (int sl = 0; sl < 32; sl++) s += g_xmp[(size_t)(bd3*32+sl)*128 + o];
    g_xm[bd3*128 + o] = s * (1.f/2048.f);
}

__global__ void k_bcast()
{
    int t = blockIdx.x*blockDim.x + threadIdx.x;
    if (t >= BN_ALL*96) return;
    int bn = t / 96, r = t - bn*96;
    int d = r >> 5, oc = (r & 31)*4;
    int b = bn / NPTS;
    float4 v = *(const float4*)&g_xm[(b*3+d)*128 + oc];
    *(float4*)&g_xcat256[((size_t)bn*3 + d)*256 + 128 + oc] = v;
}

__global__ void k_bias_i1(const float* __restrict__ wi1f, const float* __restrict__ wi1d)
{
    int t = blockIdx.x*blockDim.x + threadIdx.x;
    if (t >= BATCH*3*256) return;
    int bd3 = t >> 8, r = t & 255;
    const float* wrow = (r < 128) ? (wi1f + r*256) : (wi1d + (r-128)*256);
    float s = 0.f;
    for (int c = 0; c < 128; c++) s = fmaf(wrow[128+c], g_xm[bd3*128 + c], s);
    g_bias[bd3*256 + r] = s;
}

// ------------------------- plain p/q LNA (G=2 GEMM output), vec4 ------------
__global__ void k_lna_pd(int O, int osel)
{
    int t = blockIdx.x*blockDim.x + threadIdx.x;
    int tpp = O >> 2;
    if (t >= BN_ALL*tpp) return;
    int bn = t / tpp, oc = (t - bn*tpp)*4;
    const float* Yb = g_Y + (size_t)bn*6*O + oc;
    float4 P0 = *(const float4*)(Yb + 0*O);
    float4 P1 = *(const float4*)(Yb + 1*O);
    float4 P2 = *(const float4*)(Yb + 2*O);
    float4 Q0 = *(const float4*)(Yb + 3*O);
    float4 Q1 = *(const float4*)(Yb + 4*O);
    float4 Q2 = *(const float4*)(Yb + 5*O);
    float4 O0, O1, O2;
    #pragma unroll
    for (int c = 0; c < 4; c++){
        float o0,o1,o2;
        lna3((&P0.x)[c], (&P1.x)[c], (&P2.x)[c],
             (&Q0.x)[c], (&Q1.x)[c], (&Q2.x)[c], o0,o1,o2);
        (&O0.x)[c]=o0; (&O1.x)[c]=o1; (&O2.x)[c]=o2;
    }
    if (osel == 0){
        float* out = g_t128 + (size_t)bn*3*128 + oc;
        *(float4*)(out)=O0; *(float4*)(out+128)=O1; *(float4*)(out+256)=O2;
    } else {
        float* out = g_x0v + (size_t)bn*3*256 + oc;
        *(float4*)(out)=O0; *(float4*)(out+256)=O1; *(float4*)(out+512)=O2;
    }
}

// ------------------------- final invariant (vec4) ---------------------------
__global__ void __launch_bounds__(256) k_inv(float* __restrict__ out)
{
    __shared__ float tile[256*33];
    int n0 = blockIdx.x * 32;
    int t  = threadIdx.x;
    int pg = t >> 6;             // 0..3 -> 8 points each
    int oc = (t & 63)*4;         // 4 o-channels
    for (int pp = 0; pp < 8; pp++){
        int p = pg*8 + pp;
        size_t base = (size_t)(n0 + p)*3*256 + oc;
        float4 a0 = *(const float4*)&g_xcat256[base];
        float4 a1 = *(const float4*)&g_xcat256[base + 256];
        float4 a2 = *(const float4*)&g_xcat256[base + 512];
        float4 b0 = *(const float4*)&g_x0v[base];
        float4 b1 = *(const float4*)&g_x0v[base + 256];
        float4 b2 = *(const float4*)&g_x0v[base + 512];
        #pragma unroll
        for (int c = 0; c < 4; c++){
            float s = (&a0.x)[c]*(&b0.x)[c] + (&a1.x)[c]*(&b1.x)[c] + (&a2.x)[c]*(&b2.x)[c];
            tile[(oc + c)*33 + p] = s;
        }
    }
    __syncthreads();
    int b   = n0 / NPTS;
    int nn0 = n0 - b*NPTS;
    int p   = t & 31, og = t >> 5;
    for (int o = og; o < 256; o += 8)
        out[(size_t)(b*256 + o)*NPTS + nn0 + p] = tile[o*33 + p];
}

// ------------------------- launcher -----------------------------------------
extern "C" void kernel_launch(void* const* d_in, const int* in_sizes, int n_in,
                              void* d_out, int out_size)
{
    const float* x    = (const float*)d_in[0];
    const float* w1f  = (const float*)d_in[1];
    const float* w1d  = (const float*)d_in[2];
    const float* w2f  = (const float*)d_in[3];
    const float* w2d  = (const float*)d_in[4];
    const float* w3f  = (const float*)d_in[5];
    const float* w3d  = (const float*)d_in[6];
    const float* w4f  = (const float*)d_in[7];
    const float* w4d  = (const float*)d_in[8];
    const float* wcf  = (const float*)d_in[9];
    const float* wcd  = (const float*)d_in[10];
    const float* wi1f = (const float*)d_in[11];
    const float* wi1d = (const float*)d_in[12];
    const float* wi2f = (const float*)d_in[13];
    const float* wi2d = (const float*)d_in[14];
    float* out = (float*)d_out;

    k_prep<<<(BN_ALL+127)/128, 128>>>(x);
    k_knn_part<<<(BN_ALL*4+127)/128, 128>>>();
    k_knn_merge<<<(BN_ALL+127)/128, 128>>>();

    // ---- layer 1 (C=1 -> O=16)
    k_layer1<<<(BN_ALL*48+255)/256, 256>>>(w1f, w1d);
    k_gather<16,64><<<BN_ALL/64, 256>>>(0);

    // ---- layer 2 (C=16 -> O=32)
    k_wcomb_graph<<<(4*32*16+255)/256, 256>>>(w2f, w2d, 16, 32);
    k_hgemm<<<dim3(M_COLS/128, 1), 256>>>(0, 0, 128, 16, 240, 0, 4, 32);
    k_gather<32,32><<<BN_ALL/32, 256>>>(16);

    // ---- layer 3 (C=32 -> O=64)
    k_wcomb_graph<<<(4*64*32+255)/256, 256>>>(w3f, w3d, 32, 64);
    k_hgemm<<<dim3(M_COLS/128, 2), 256>>>(0, 0, 256, 32, 240, 16, 4, 64);
    k_gather<64,16><<<BN_ALL/16, 256>>>(48);

    // ---- layer 4 (C=64 -> O=128)
    k_wcomb_graph<<<(4*128*64+255)/256, 256>>>(w4f, w4d, 64, 128);
    k_hgemm<<<dim3(M_COLS/128, 4), 256>>>(0, 0, 512, 64, 240, 48, 4, 128);
    k_gather<128,8><<<BN_ALL/8, 256>>>(112);

    // ---- concat layer (wcf 128x240, wcd 1x240)
    k_wcomb_c<<<(128*240+255)/256, 256>>>(wcf);
    k_hgemm<<<dim3(M_COLS/128, 1), 256>>>(0, 0, 128, 240, 240, 0, 1, 128);
    k_dc<<<(M_COLS*32+255)/256, 256>>>(wcd);
    k_lna_c<<<(BN_ALL*32+255)/256, 256>>>();

    // ---- xm mean over N + broadcast into channels [128,256)
    k_xm_part<<<BATCH*3*32, 128>>>();
    k_xm_final<<<(BATCH*3*128+255)/256, 256>>>();
    k_bcast<<<(BN_ALL*96+255)/256, 256>>>();

    // ---- i1 (wi1f/wi1d 128x256; contract 128 + xm bias)
    k_wcomb_i1<<<(256*128+255)/256, 256>>>(wi1f, wi1d);
    k_bias_i1<<<(BATCH*3*256+255)/256, 256>>>(wi1f, wi1d);
    k_hgemm<<<dim3(M_COLS/128, 2), 256>>>(1, 1, 256, 128, 256, 0, 2, 128);
    k_lna_pd<<<(BN_ALL*32+255)/256, 256>>>(128, 0);

    // ---- i2 (wi2f/wi2d 256x128)
    k_wcomb_i2<<<(512*128+255)/256, 256>>>(wi2f, wi2d);
    k_hgemm<<<dim3(M_COLS/128, 4), 256>>>(2, 0, 512, 128, 128, 0, 2, 256);
    k_lna_pd<<<(BN_ALL*64+255)/256, 256>>>(256, 1);

    // ---- invariant output (B,256,N)
    k_inv<<<BN_ALL/32, 256>>>(out);
}